// round 3
// baseline (speedup 1.0000x reference)
#include <cuda_runtime.h>
#include <math.h>
#include <float.h>

#define BB 64
#define TT 4096
#define UU 256
#define DD 256
#define NSPLIT 16
#define TC (TT / NSPLIT)   // 256 tokens per split (strided)

// Scratch (no allocations allowed in kernel_launch)
__device__ float g_state[BB * UU];
__device__ float g_scores[BB * TT];
__device__ float g_pm[BB * NSPLIT];
__device__ float g_ps[BB * NSPLIT];
__device__ float g_pct[BB * NSPLIT * UU];
__device__ float g_m[BB];
__device__ float g_s[BB];

// ---------------------------------------------------------------------------
// Kernel A: state[b,u] = sum_d decoder_s[b,d] * Wa_w[d,u] + Wa_b[u]
// grid = B, block = 256 threads (one per u). W stays L2-resident (256 KB).
// ---------------------------------------------------------------------------
__global__ void state_kernel(const float* __restrict__ ds,
                             const float* __restrict__ W,
                             const float* __restrict__ bias) {
    __shared__ float sh[DD];
    int b = blockIdx.x;
    int u = threadIdx.x;
    sh[u] = ds[b * DD + u];
    __syncthreads();
    float acc = bias[u];
#pragma unroll 8
    for (int d = 0; d < DD; d++) {
        acc = fmaf(sh[d], W[d * UU + u], acc);
    }
    g_state[b * UU + u] = acc;
}

// ---------------------------------------------------------------------------
// Kernel B: fused score + online softmax + context accumulation.
// grid = (NSPLIT, B), block = 256 threads = 8 warps.
// STRIDED split mapping: split s owns tokens t = s + NSPLIT*j, j in [0,TC).
// Within a split, warp w takes j = w, w+8, ... Token index is monotone in j,
// and the mask is left-packed, so the warp checks mask BEFORE loading h and
// breaks at the first masked token. Every CTA of batch b therefore processes
// ~length/NSPLIT tokens -> balanced load across the grid. Each valid h
// element is read from HBM exactly once (dot + context use same registers).
// ---------------------------------------------------------------------------
__global__ void __launch_bounds__(256, 4)
score_ctx_kernel(const float* __restrict__ h, const int* __restrict__ mask) {
    int split = blockIdx.x;
    int b     = blockIdx.y;
    int tid   = threadIdx.x;
    int warp  = tid >> 5;
    int lane  = tid & 31;

    // state in registers: lane holds u = 4*lane..4*lane+3 and +128..+131
    const float4* stp = reinterpret_cast<const float4*>(g_state + b * UU);
    float4 st0 = stp[lane];
    float4 st1 = stp[lane + 32];

    float m = -FLT_MAX;
    float s = 0.0f;
    float4 c0 = make_float4(0.f, 0.f, 0.f, 0.f);
    float4 c1 = make_float4(0.f, 0.f, 0.f, 0.f);

    const float4* hb = reinterpret_cast<const float4*>(h) + (long)b * TT * 64;
    const int*    mb = mask + b * TT;

#pragma unroll 2
    for (int j = warp; j < TC; j += 8) {
        int t = split + NSPLIT * j;             // strided token for this split
        int mk = mb[t];
        if (!mk) break;                         // left-packed: rest is padding

        const float4* hp = hb + (long)t * 64;   // 64 float4 per token
        float4 h0 = hp[lane];
        float4 h1 = hp[lane + 32];

        float p = h0.x * st0.x + h0.y * st0.y + h0.z * st0.z + h0.w * st0.w
                + h1.x * st1.x + h1.y * st1.y + h1.z * st1.z + h1.w * st1.w;
#pragma unroll
        for (int o = 16; o; o >>= 1)
            p += __shfl_xor_sync(0xffffffffu, p, o);

        if (lane == 0) g_scores[b * TT + t] = p;

        float nm    = fmaxf(m, p);
        float scale = __expf(m - nm);           // first token: underflows to 0
        float pe    = __expf(p - nm);
        s = s * scale + pe;
        c0.x = fmaf(pe, h0.x, c0.x * scale);
        c0.y = fmaf(pe, h0.y, c0.y * scale);
        c0.z = fmaf(pe, h0.z, c0.z * scale);
        c0.w = fmaf(pe, h0.w, c0.w * scale);
        c1.x = fmaf(pe, h1.x, c1.x * scale);
        c1.y = fmaf(pe, h1.y, c1.y * scale);
        c1.z = fmaf(pe, h1.z, c1.z * scale);
        c1.w = fmaf(pe, h1.w, c1.w * scale);
        m = nm;
    }

    // Combine the 8 warps' (m, s, ct) within the block.
    __shared__ float sh_m[8];
    __shared__ float sh_s[8];
    __shared__ float sh_ct[8][UU];
    float* ctw = sh_ct[warp];
    ctw[4 * lane + 0]   = c0.x;
    ctw[4 * lane + 1]   = c0.y;
    ctw[4 * lane + 2]   = c0.z;
    ctw[4 * lane + 3]   = c0.w;
    ctw[4 * lane + 128] = c1.x;
    ctw[4 * lane + 129] = c1.y;
    ctw[4 * lane + 130] = c1.z;
    ctw[4 * lane + 131] = c1.w;
    if (lane == 0) { sh_m[warp] = m; sh_s[warp] = s; }
    __syncthreads();

    float bm = -FLT_MAX;
#pragma unroll
    for (int w = 0; w < 8; w++) bm = fmaxf(bm, sh_m[w]);
    float bs = 0.0f;
    float bc = 0.0f;
#pragma unroll
    for (int w = 0; w < 8; w++) {
        float sc = __expf(sh_m[w] - bm);   // empty warp: underflows to 0
        bs += sc * sh_s[w];
        bc = fmaf(sc, sh_ct[w][tid], bc);
    }
    int pidx = b * NSPLIT + split;
    if (tid == 0) { g_pm[pidx] = bm; g_ps[pidx] = bs; }
    g_pct[pidx * UU + tid] = bc;
}

// ---------------------------------------------------------------------------
// Kernel C: reduce over splits -> ct_sum (normalized) and per-batch (m, s).
// grid = B, block = 256 (one thread per u). With strided splits and
// length >= T/4, every split has >= 64 valid tokens -> all partials finite.
// ---------------------------------------------------------------------------
__global__ void reduce_kernel(float* __restrict__ out_ct) {
    int b   = blockIdx.x;
    int tid = threadIdx.x;

    float m = -FLT_MAX;
#pragma unroll
    for (int w = 0; w < NSPLIT; w++) m = fmaxf(m, g_pm[b * NSPLIT + w]);

    float s = 0.0f;
    float c = 0.0f;
#pragma unroll
    for (int w = 0; w < NSPLIT; w++) {
        float sc = __expf(g_pm[b * NSPLIT + w] - m);
        s += sc * g_ps[b * NSPLIT + w];
        c = fmaf(sc, g_pct[(b * NSPLIT + w) * UU + tid], c);
    }
    out_ct[b * UU + tid] = c / s;
    if (tid == 0) { g_m[b] = m; g_s[b] = s; }
}

// ---------------------------------------------------------------------------
// Kernel D: alpha[b,t] = mask ? exp(score - m_b) / s_b : 0
// (g_scores is only defined where mask != 0 — guarded read.)
// ---------------------------------------------------------------------------
__global__ void alpha_kernel(const int* __restrict__ mask,
                             float* __restrict__ out_alpha) {
    int i = blockIdx.x * blockDim.x + threadIdx.x;
    if (i >= BB * TT) return;
    int b = i >> 12;   // / TT
    float a = 0.0f;
    if (mask[i]) {
        a = __expf(g_scores[i] - g_m[b]) * (1.0f / g_s[b]);
    }
    out_alpha[i] = a;
}

// ---------------------------------------------------------------------------
extern "C" void kernel_launch(void* const* d_in, const int* in_sizes, int n_in,
                              void* d_out, int out_size) {
    const float* encoder_h = (const float*)d_in[0];  // [B, T, U]
    const float* decoder_s = (const float*)d_in[1];  // [B, D]
    const int*   mask      = (const int*)d_in[2];    // [B, T]
    const float* Wa_w      = (const float*)d_in[3];  // [D, U]
    const float* Wa_b      = (const float*)d_in[4];  // [U]

    float* out_ct    = (float*)d_out;            // [B, U]
    float* out_alpha = out_ct + BB * UU;         // [B, T, 1]

    state_kernel<<<BB, 256>>>(decoder_s, Wa_w, Wa_b);

    dim3 gridB(NSPLIT, BB);
    score_ctx_kernel<<<gridB, 256>>>(encoder_h, mask);

    reduce_kernel<<<BB, 256>>>(out_ct);

    alpha_kernel<<<(BB * TT + 255) / 256, 256>>>(mask, out_alpha);
}

// round 17
// speedup vs baseline: 1.1015x; 1.1015x over previous
#include <cuda_runtime.h>
#include <math.h>
#include <float.h>
#include <stdint.h>

#define BB 64
#define TT 4096
#define UU 256
#define DD 256
#define NSPLIT 16
#define TC (TT / NSPLIT)   // 256 max tokens per split (strided)
#define TILE 8             // tokens per smem tile (8 KB)
#define NBUF 3             // cp.async ring depth

// Scratch (no allocations allowed in kernel_launch)
__device__ float g_state[BB * UU];
__device__ int   g_len[BB];
__device__ float g_scores[BB * TT];
__device__ float g_pm[BB * NSPLIT];
__device__ float g_ps[BB * NSPLIT];
__device__ float g_pct[BB * NSPLIT * UU];

// ---------------------------------------------------------------------------
// Kernel A: state[b,u] = decoder_s[b] . Wa_w[:,u] + Wa_b[u]   AND
//           g_len[b]   = sum_t mask[b,t]  (mask is 0/1, left-packed)
// ---------------------------------------------------------------------------
__global__ void state_kernel(const float* __restrict__ ds,
                             const float* __restrict__ W,
                             const float* __restrict__ bias,
                             const int* __restrict__ mask) {
    __shared__ float sh[DD];
    __shared__ int shl[8];
    int b = blockIdx.x;
    int u = threadIdx.x;
    sh[u] = ds[b * DD + u];

    const int* mb = mask + b * TT;
    int acc_i = 0;
#pragma unroll
    for (int k = 0; k < 16; k++) acc_i += mb[u + 256 * k];
#pragma unroll
    for (int o = 16; o; o >>= 1)
        acc_i += __shfl_xor_sync(0xffffffffu, acc_i, o);
    if ((u & 31) == 0) shl[u >> 5] = acc_i;
    __syncthreads();
    if (u == 0) {
        int L = 0;
#pragma unroll
        for (int w = 0; w < 8; w++) L += shl[w];
        g_len[b] = L;
    }

    float acc = bias[u];
#pragma unroll 8
    for (int d = 0; d < DD; d++) {
        acc = fmaf(sh[d], W[d * UU + u], acc);
    }
    g_state[b * UU + u] = acc;
}

// ---------------------------------------------------------------------------
// cp.async helpers
// ---------------------------------------------------------------------------
__device__ __forceinline__ void issue_tile(const float* __restrict__ hb,
                                           float* __restrict__ bufslot,
                                           int tile, int ntiles, int jcnt,
                                           int split, int tid) {
    if (tile < ntiles) {
        // 8 tokens x 1 KB = 512 16B chunks; 2 per thread
#pragma unroll
        for (int q = 0; q < 2; q++) {
            int cch = tid + q * 256;
            int k   = cch >> 6;          // token slot 0..7
            int off = (cch & 63) * 4;    // float offset within token
            int j   = tile * TILE + k;
            if (j >= jcnt) j = jcnt - 1; // clamp: finite data, pe forced to 0
            const float* src = hb + (long)(split + NSPLIT * j) * UU + off;
            uint32_t dst = (uint32_t)__cvta_generic_to_shared(bufslot + k * UU + off);
            asm volatile("cp.async.cg.shared.global [%0], [%1], 16;\n"
                         :: "r"(dst), "l"(src));
        }
    }
    asm volatile("cp.async.commit_group;\n");   // empty groups at tail keep
}                                               // wait_group arithmetic exact

// ---------------------------------------------------------------------------
// Kernel B: fused score + online softmax + context accumulation.
// grid = (NSPLIT, B), block = 256 = 8 warps.
// Strided split: split s owns tokens t = s + 16*j; jcnt is a register value
// (no data-dependent branches). Tokens stream through a 3-deep cp.async smem
// ring (2 tiles = 16 KB in flight per CTA; ~8 CTAs/SM -> ~128 KB in flight
// per SM, far above the ~18 KB needed to cover DRAM latency). Per tile:
// warp w computes token w's dot from smem (conflict-free float4 LDS), scores
// shared via sh_sc; then EVERY thread updates its u-column for all 8 tokens
// in one online-softmax step (serial exp chain per 8 tokens, single scalar
// context accumulator per thread, no per-warp partials to merge).
// Slot-reuse safety: iteration `tile` overwrites slot (tile+2)%3 ==
// (tile-1)%3, whose readers all passed this iteration's __syncthreads().
// ---------------------------------------------------------------------------
__global__ void __launch_bounds__(256)
score_ctx_kernel(const float* __restrict__ h) {
    __shared__ float buf[NBUF][TILE * UU];   // 3 x 8 KB
    __shared__ float sh_sc[TILE];

    int split = blockIdx.x;
    int b     = blockIdx.y;
    int tid   = threadIdx.x;
    int warp  = tid >> 5;
    int lane  = tid & 31;

    int len    = g_len[b];
    int jcnt   = (len - split + NSPLIT - 1) / NSPLIT;  // >= 64 (len >= T/4)
    int ntiles = (jcnt + TILE - 1) / TILE;

    const float* hb = h + (long)b * TT * UU;

    issue_tile(hb, buf[0], 0, ntiles, jcnt, split, tid);
    issue_tile(hb, buf[1], 1, ntiles, jcnt, split, tid);

    const float4* stp = reinterpret_cast<const float4*>(g_state + b * UU);
    float4 st0 = stp[lane];
    float4 st1 = stp[lane + 32];
    float* scrow = g_scores + b * TT;

    float m = -FLT_MAX;
    float s = 0.0f;
    float c = 0.0f;

    for (int tile = 0; tile < ntiles; tile++) {
        asm volatile("cp.async.wait_group 1;\n");
        __syncthreads();
        const float* bp = buf[tile % NBUF];

        // --- dot: warp w handles token slot w ---
        {
            int j = tile * TILE + warp;
            const float4* r = reinterpret_cast<const float4*>(bp + warp * UU);
            float4 a0 = r[lane];
            float4 a1 = r[lane + 32];
            float p = a0.x * st0.x + a0.y * st0.y + a0.z * st0.z + a0.w * st0.w
                    + a1.x * st1.x + a1.y * st1.y + a1.z * st1.z + a1.w * st1.w;
#pragma unroll
            for (int o = 16; o; o >>= 1)
                p += __shfl_xor_sync(0xffffffffu, p, o);
            if (lane == 0) {
                if (j < jcnt) {
                    sh_sc[warp] = p;
                    scrow[split + NSPLIT * j] = p;
                } else {
                    sh_sc[warp] = -FLT_MAX;   // clamped duplicate -> weight 0
                }
            }
        }
        __syncthreads();

        // --- online softmax update over 8 tokens at once ---
        float sc[TILE];
#pragma unroll
        for (int k = 0; k < TILE; k++) sc[k] = sh_sc[k];
        float tm = sc[0];
#pragma unroll
        for (int k = 1; k < TILE; k++) tm = fmaxf(tm, sc[k]);
        float nm    = fmaxf(m, tm);
        float scale = __expf(m - nm);         // first tile: underflows to 0
        float pe[TILE];
        float ps = 0.0f;
#pragma unroll
        for (int k = 0; k < TILE; k++) { pe[k] = __expf(sc[k] - nm); ps += pe[k]; }
        s = s * scale + ps;
        float acc = c * scale;
#pragma unroll
        for (int k = 0; k < TILE; k++)
            acc = fmaf(pe[k], bp[k * UU + tid], acc);
        c = acc;
        m = nm;

        issue_tile(hb, buf[(tile + 2) % NBUF], tile + 2, ntiles, jcnt, split, tid);
    }

    int pidx = b * NSPLIT + split;
    g_pct[pidx * UU + tid] = c;
    if (tid == 0) { g_pm[pidx] = m; g_ps[pidx] = s; }
}

// ---------------------------------------------------------------------------
// Kernel C (fused): per-batch split reduction -> ct_sum, then alpha for the
// same batch. grid = B, block = 256. (m, s) stay in smem — no extra global
// round-trip, one fewer launch than the reduce+alpha pair.
// ---------------------------------------------------------------------------
__global__ void __launch_bounds__(256)
finalize_kernel(const int* __restrict__ mask,
                float* __restrict__ out_ct,
                float* __restrict__ out_alpha) {
    __shared__ float sh_m, sh_sinv;
    int b   = blockIdx.x;
    int tid = threadIdx.x;

    // --- split reduction (one thread per u) ---
    float m = -FLT_MAX;
#pragma unroll
    for (int w = 0; w < NSPLIT; w++) m = fmaxf(m, g_pm[b * NSPLIT + w]);

    float s = 0.0f;
    float c = 0.0f;
#pragma unroll
    for (int w = 0; w < NSPLIT; w++) {
        float sc = __expf(g_pm[b * NSPLIT + w] - m);
        s += sc * g_ps[b * NSPLIT + w];
        c = fmaf(sc, g_pct[(b * NSPLIT + w) * UU + tid], c);
    }
    out_ct[b * UU + tid] = c / s;   // len >= T/4 guarantees s > 0
    if (tid == 0) { sh_m = m; sh_sinv = 1.0f / s; }
    __syncthreads();

    float mb   = sh_m;
    float sinv = sh_sinv;

    // --- alpha for this batch: 1024 quads, 4 per thread, unrolled (MLP 8) ---
    const int4*   mrow = reinterpret_cast<const int4*>(mask + b * TT);
    const float4* srow = reinterpret_cast<const float4*>(g_scores + b * TT);
    float4*       arow = reinterpret_cast<float4*>(out_alpha + b * TT);
#pragma unroll
    for (int q = 0; q < 4; q++) {
        int i4 = tid + q * 256;
        int4   mk = mrow[i4];
        float4 sc = srow[i4];
        float4 a;
        a.x = mk.x ? __expf(sc.x - mb) * sinv : 0.0f;
        a.y = mk.y ? __expf(sc.y - mb) * sinv : 0.0f;
        a.z = mk.z ? __expf(sc.z - mb) * sinv : 0.0f;
        a.w = mk.w ? __expf(sc.w - mb) * sinv : 0.0f;
        arow[i4] = a;
    }
}

// ---------------------------------------------------------------------------
extern "C" void kernel_launch(void* const* d_in, const int* in_sizes, int n_in,
                              void* d_out, int out_size) {
    const float* encoder_h = (const float*)d_in[0];  // [B, T, U]
    const float* decoder_s = (const float*)d_in[1];  // [B, D]
    const int*   mask      = (const int*)d_in[2];    // [B, T]
    const float* Wa_w      = (const float*)d_in[3];  // [D, U]
    const float* Wa_b      = (const float*)d_in[4];  // [U]

    float* out_ct    = (float*)d_out;            // [B, U]
    float* out_alpha = out_ct + BB * UU;         // [B, T, 1]

    state_kernel<<<BB, 256>>>(decoder_s, Wa_w, Wa_b, mask);

    dim3 gridB(NSPLIT, BB);
    score_ctx_kernel<<<gridB, 256>>>(encoder_h);

    finalize_kernel<<<BB, 256>>>(mask, out_ct, out_alpha);
}